// round 1
// baseline (speedup 1.0000x reference)
#include <cuda_runtime.h>
#include <cstdint>

// NumericalMarkowitz: B=1024 items, N=128.
// 1 CTA (128 threads) per item. Thread t owns row t of Q as 64 packed f32x2
// registers. Matvec = 64 fma.rn.f32x2 per thread, no cross-thread reduce.
// Projection = warm-started bracket-guarded Newton on the capped-simplex
// dual variable tau, executed by one (rotating) warp per iteration.

typedef unsigned long long ull;

#define N_DIM   128
#define N_ITERS 300
#define MW      1.0f

__device__ __forceinline__ ull pk2(float x, float y) {
    ull r; asm("mov.b64 %0, {%1, %2};" : "=l"(r) : "f"(x), "f"(y)); return r;
}
__device__ __forceinline__ void upk2(ull a, float& x, float& y) {
    asm("mov.b64 {%0, %1}, %2;" : "=f"(x), "=f"(y) : "l"(a));
}
__device__ __forceinline__ ull fma2(ull a, ull b, ull c) {
    ull d; asm("fma.rn.f32x2 %0, %1, %2, %3;" : "=l"(d) : "l"(a), "l"(b), "l"(c)); return d;
}
__device__ __forceinline__ ull mul2(ull a, ull b) {
    ull d; asm("mul.rn.f32x2 %0, %1, %2;" : "=l"(d) : "l"(a), "l"(b)); return d;
}
__device__ __forceinline__ ull add2(ull a, ull b) {
    ull d; asm("add.rn.f32x2 %0, %1, %2;" : "=l"(d) : "l"(a), "l"(b)); return d;
}

// Dynamic smem layout (floats):
//   [0,16384)        : C tile (item's covmat_sqrt), row-major C[k][c]
//   [16384,16512)    : y
//   [16512,16640)    : v
//   [16640,16768)    : w
//   [16768,16776)    : reduction scratch (4 warp partials) + warm tau at [4]
#define SMEM_FLOATS (16384 + 128 + 128 + 128 + 8)

extern __shared__ float smem_f[];

__global__ void __launch_bounds__(128, 3)
markowitz_kernel(const float* __restrict__ rets,
                 const float* __restrict__ covmat,
                 const float* __restrict__ gamma_sqrt,
                 const float* __restrict__ alpha,
                 float* __restrict__ out)
{
    const int b    = blockIdx.x;
    const int t    = threadIdx.x;
    const int lane = t & 31;
    const int wid  = t >> 5;

    float* sC = smem_f;
    float* sY = smem_f + 16384;
    float* sV = sY + 128;
    float* sW = sV + 128;
    float* sR = sW + 128;   // sR[0..3] warp partials, sR[4] warm-start tau

    // ---- load C tile (64KB) coalesced into smem ----
    {
        const float4* Cg  = reinterpret_cast<const float4*>(covmat + (size_t)b * (N_DIM * N_DIM));
        float4*       sC4 = reinterpret_cast<float4*>(sC);
        #pragma unroll
        for (int i = 0; i < 32; i++) sC4[i * 128 + t] = Cg[i * 128 + t];
    }
    const float myret = rets[b * N_DIM + t];
    const float g     = gamma_sqrt[b];
    const float g2    = g * g;
    const float aab   = fabsf(alpha[b]);
    __syncthreads();

    // ---- build Q row t: Q[t][c] = g2 * sum_k C[k][t]*C[k][c]  (+|alpha| on diag)
    ull q[64];
    #pragma unroll
    for (int j = 0; j < 64; j++) q[j] = 0ULL;   // (+0.0f, +0.0f)

    for (int k = 0; k < N_DIM; k++) {
        const float a  = sC[k * 128 + t];            // coalesced
        const ull   aa = pk2(a, a);
        const ulonglong2* row = reinterpret_cast<const ulonglong2*>(sC + k * 128);
        #pragma unroll
        for (int j = 0; j < 32; j++) {
            ulonglong2 bb = row[j];                  // broadcast, conflict-free
            q[2 * j]     = fma2(aa, bb.x, q[2 * j]);
            q[2 * j + 1] = fma2(aa, bb.y, q[2 * j + 1]);
        }
    }
    {
        const ull g2p = pk2(g2, g2);
        #pragma unroll
        for (int j = 0; j < 64; j++) q[j] = mul2(q[j], g2p);
        // diagonal element (t,t) lives in q[t>>1], half (t&1)
        float x, y; upk2(q[t >> 1], x, y);
        if (t & 1) y += aab; else x += aab;
        q[t >> 1] = pk2(x, y);
    }

    // ---- step = 1 / (2 * ||Q||_F) ----
    {
        ull sacc = 0ULL;
        #pragma unroll
        for (int j = 0; j < 64; j++) sacc = fma2(q[j], q[j], sacc);
        float sx, sy; upk2(sacc, sx, sy);
        float ssq = sx + sy;
        #pragma unroll
        for (int o = 16; o > 0; o >>= 1) ssq += __shfl_xor_sync(0xffffffffu, ssq, o);
        if (lane == 0) sR[wid] = ssq;
    }
    __syncthreads();
    const float Ssum = sR[0] + sR[1] + sR[2] + sR[3];
    const float step = 1.0f / (2.0f * sqrtf(Ssum));

    // ---- FISTA init ----
    sY[t] = 1.0f / 128.0f;
    sW[t] = 1.0f / 128.0f;
    if (t == 0) sR[4] = 3.0e38f;   // invalid warm tau -> midpoint on first use
    float tk = 1.0f;
    __syncthreads();

    for (int it = 0; it < N_ITERS; it++) {
        // ---- matvec: qy = Q[t][:] . y ----
        ull a0 = 0ULL, a1 = 0ULL, a2 = 0ULL, a3 = 0ULL;
        const ulonglong2* yy = reinterpret_cast<const ulonglong2*>(sY);
        #pragma unroll
        for (int j = 0; j < 16; j++) {
            ulonglong2 y0 = yy[2 * j];
            ulonglong2 y1 = yy[2 * j + 1];
            a0 = fma2(q[4 * j],     y0.x, a0);
            a1 = fma2(q[4 * j + 1], y0.y, a1);
            a2 = fma2(q[4 * j + 2], y1.x, a2);
            a3 = fma2(q[4 * j + 3], y1.y, a3);
        }
        a0 = add2(add2(a0, a1), add2(a2, a3));
        float ox, oy; upk2(a0, ox, oy);
        const float qy = ox + oy;

        const float yv = sY[t];
        // v = y - step * (2*Qy - rets)
        const float v = fmaf(-step, fmaf(2.0f, qy, -myret), yv);
        sV[t] = v;

        // t-sequence (every thread tracks it; only proj warp consumes coef)
        const float tn   = 0.5f * (1.0f + sqrtf(fmaf(4.0f * tk, tk, 1.0f)));
        const float coef = (tk - 1.0f) / tn;
        tk = tn;

        __syncthreads();   // v complete; y/w reads of this iter done

        if (wid == (it & 3)) {
            // ---- capped-simplex projection of sV, warp-local ----
            const float4 v4 = reinterpret_cast<const float4*>(sV)[lane];
            const float4 w4 = reinterpret_cast<const float4*>(sW)[lane];

            float mn = fminf(fminf(v4.x, v4.y), fminf(v4.z, v4.w));
            float mx = fmaxf(fmaxf(v4.x, v4.y), fmaxf(v4.z, v4.w));
            #pragma unroll
            for (int o = 16; o > 0; o >>= 1) {
                mn = fminf(mn, __shfl_xor_sync(0xffffffffu, mn, o));
                mx = fmaxf(mx, __shfl_xor_sync(0xffffffffu, mx, o));
            }
            float lo = mn - MW;
            float hi = mx;

            float tau = sR[4];                       // warm start
            if (!(tau > lo && tau < hi)) tau = 0.5f * (lo + hi);

            // guarded Newton / active-set iteration on
            //   s(tau) = sum clip(v - tau, 0, MW) = 1
            #pragma unroll 1
            for (int n = 0; n < 32; n++) {
                float sv  = 0.0f;
                int   cnt = 0;
                {
                    float z;
                    z = v4.x - tau; if (z > 0.0f && z < MW) { sv += v4.x; cnt += 1; } else if (z >= MW) cnt += 4096;
                    z = v4.y - tau; if (z > 0.0f && z < MW) { sv += v4.y; cnt += 1; } else if (z >= MW) cnt += 4096;
                    z = v4.z - tau; if (z > 0.0f && z < MW) { sv += v4.z; cnt += 1; } else if (z >= MW) cnt += 4096;
                    z = v4.w - tau; if (z > 0.0f && z < MW) { sv += v4.w; cnt += 1; } else if (z >= MW) cnt += 4096;
                }
                #pragma unroll
                for (int o = 16; o > 0; o >>= 1) {
                    sv  += __shfl_xor_sync(0xffffffffu, sv, o);
                    cnt += __shfl_xor_sync(0xffffffffu, cnt, o);
                }
                const int   nf = cnt & 4095;
                const int   nu = cnt >> 12;
                const float s  = sv - (float)nf * tau + MW * (float)nu;
                if (s > 1.0f) lo = tau; else hi = tau;

                float tnew;
                if (nf > 0) tnew = (sv + MW * (float)nu - 1.0f) / (float)nf;
                else        tnew = 0.5f * (lo + hi);
                if (!(tnew > lo && tnew < hi)) tnew = 0.5f * (lo + hi);
                if (tnew == tau) break;              // active-set fixed point
                tau = tnew;
            }

            // final classification at tau + reference tau re-derivation
            float sv  = 0.0f;
            int   cnt = 0;
            bool fr0, fr1, fr2, fr3, up0, up1, up2, up3;
            {
                float z;
                z = v4.x - tau; fr0 = (z > 0.0f) && (z < MW); up0 = (z >= MW);
                if (fr0) { sv += v4.x; cnt += 1; } if (up0) cnt += 4096;
                z = v4.y - tau; fr1 = (z > 0.0f) && (z < MW); up1 = (z >= MW);
                if (fr1) { sv += v4.y; cnt += 1; } if (up1) cnt += 4096;
                z = v4.z - tau; fr2 = (z > 0.0f) && (z < MW); up2 = (z >= MW);
                if (fr2) { sv += v4.z; cnt += 1; } if (up2) cnt += 4096;
                z = v4.w - tau; fr3 = (z > 0.0f) && (z < MW); up3 = (z >= MW);
                if (fr3) { sv += v4.w; cnt += 1; } if (up3) cnt += 4096;
            }
            #pragma unroll
            for (int o = 16; o > 0; o >>= 1) {
                sv  += __shfl_xor_sync(0xffffffffu, sv, o);
                cnt += __shfl_xor_sync(0xffffffffu, cnt, o);
            }
            const int   nf    = cnt & 4095;
            const int   nu    = cnt >> 12;
            const float nfree = (float)(nf > 0 ? nf : 1);
            const float tauf  = (sv + MW * (float)nu - 1.0f) / nfree;

            float4 wn, yn;
            wn.x = fr0 ? (v4.x - tauf) : (up0 ? MW : 0.0f);
            wn.y = fr1 ? (v4.y - tauf) : (up1 ? MW : 0.0f);
            wn.z = fr2 ? (v4.z - tauf) : (up2 ? MW : 0.0f);
            wn.w = fr3 ? (v4.w - tauf) : (up3 ? MW : 0.0f);
            yn.x = fmaf(coef, wn.x - w4.x, wn.x);
            yn.y = fmaf(coef, wn.y - w4.y, wn.y);
            yn.z = fmaf(coef, wn.z - w4.z, wn.z);
            yn.w = fmaf(coef, wn.w - w4.w, wn.w);

            reinterpret_cast<float4*>(sW)[lane] = wn;
            reinterpret_cast<float4*>(sY)[lane] = yn;
            if (lane == 0) sR[4] = tau;              // warm start for next iter
        }
        __syncthreads();   // w, y ready for next iteration
    }

    out[b * N_DIM + t] = sW[t];
}

extern "C" void kernel_launch(void* const* d_in, const int* in_sizes, int n_in,
                              void* d_out, int out_size)
{
    const float* rets   = (const float*)d_in[0];
    const float* covmat = (const float*)d_in[1];
    const float* gsqrt  = (const float*)d_in[2];
    const float* alph   = (const float*)d_in[3];
    float*       out    = (float*)d_out;

    const int B = in_sizes[2];   // gamma_sqrt element count = batch
    const size_t smem_bytes = SMEM_FLOATS * sizeof(float);

    static bool attr_set = false;
    if (!attr_set) {
        cudaFuncSetAttribute(markowitz_kernel,
                             cudaFuncAttributeMaxDynamicSharedMemorySize,
                             (int)smem_bytes);
        attr_set = true;
    }

    markowitz_kernel<<<B, N_DIM, smem_bytes>>>(rets, covmat, gsqrt, alph, out);
}

// round 4
// speedup vs baseline: 1.0869x; 1.0869x over previous
#include <cuda_runtime.h>
#include <cstdint>

// NumericalMarkowitz: B=1024 items, N=128.
// 1 CTA (128 threads) per item. Thread t owns row t of Q as 64 packed f32x2
// registers. Matvec = 64 fma.rn.f32x2 per thread, no cross-thread reduce.
// Projection = warm-started bracket-guarded Newton on the capped-simplex
// dual tau, one rotating warp. Integer warp reductions use redux.sync.add.u32
// (supported on sm_103); float reductions use shfl butterflies.
// FISTA loop exits early once (w, y) is bitwise frozen (provably identical
// to running the remaining reference iterations).

typedef unsigned long long ull;

#define N_DIM   128
#define N_ITERS 300
#define MW      1.0f

__device__ __forceinline__ ull pk2(float x, float y) {
    ull r; asm("mov.b64 %0, {%1, %2};" : "=l"(r) : "f"(x), "f"(y)); return r;
}
__device__ __forceinline__ void upk2(ull a, float& x, float& y) {
    asm("mov.b64 {%0, %1}, %2;" : "=f"(x), "=f"(y) : "l"(a));
}
__device__ __forceinline__ ull fma2(ull a, ull b, ull c) {
    ull d; asm("fma.rn.f32x2 %0, %1, %2, %3;" : "=l"(d) : "l"(a), "l"(b), "l"(c)); return d;
}
__device__ __forceinline__ ull mul2(ull a, ull b) {
    ull d; asm("mul.rn.f32x2 %0, %1, %2;" : "=l"(d) : "l"(a), "l"(b)); return d;
}
__device__ __forceinline__ ull add2(ull a, ull b) {
    ull d; asm("add.rn.f32x2 %0, %1, %2;" : "=l"(d) : "l"(a), "l"(b)); return d;
}

// Integer warp reduction: supported on sm_103 (Ampere+).
__device__ __forceinline__ unsigned wredux_addu(unsigned v) {
    unsigned r; asm volatile("redux.sync.add.u32 %0, %1, 0xffffffff;" : "=r"(r) : "r"(v)); return r;
}
__device__ __forceinline__ float wshfl_add(float v) {
    #pragma unroll
    for (int o = 16; o > 0; o >>= 1) v += __shfl_xor_sync(0xffffffffu, v, o);
    return v;
}

// Dynamic smem layout (floats):
//   [0,16384)     : C tile (item's covmat_sqrt), row-major C[k][c]
//   [16384,16512) : y
//   [16512,16640) : v
//   [16640,16768) : w
//   [16768,16776) : sR: [0..3] warp partials, [4] warm tau, [5] converged flag
#define SMEM_FLOATS (16384 + 128 + 128 + 128 + 8)

extern __shared__ float smem_f[];

__global__ void __launch_bounds__(128, 3)
markowitz_kernel(const float* __restrict__ rets,
                 const float* __restrict__ covmat,
                 const float* __restrict__ gamma_sqrt,
                 const float* __restrict__ alpha,
                 float* __restrict__ out)
{
    const int b    = blockIdx.x;
    const int t    = threadIdx.x;
    const int lane = t & 31;
    const int wid  = t >> 5;

    float* sC = smem_f;
    float* sY = smem_f + 16384;
    float* sV = sY + 128;
    float* sW = sV + 128;
    float* sR = sW + 128;

    // ---- load C tile (64KB) coalesced into smem ----
    {
        const float4* Cg  = reinterpret_cast<const float4*>(covmat + (size_t)b * (N_DIM * N_DIM));
        float4*       sC4 = reinterpret_cast<float4*>(sC);
        #pragma unroll
        for (int i = 0; i < 32; i++) sC4[i * 128 + t] = Cg[i * 128 + t];
    }
    const float myret = rets[b * N_DIM + t];
    const float g     = gamma_sqrt[b];
    const float g2    = g * g;
    const float aab   = fabsf(alpha[b]);
    __syncthreads();

    // ---- build Q row t: Q[t][c] = g2 * sum_k C[k][t]*C[k][c]  (+|alpha| on diag)
    ull q[64];
    #pragma unroll
    for (int j = 0; j < 64; j++) q[j] = 0ULL;

    for (int k = 0; k < N_DIM; k++) {
        const float a  = sC[k * 128 + t];            // coalesced
        const ull   aa = pk2(a, a);
        const ulonglong2* row = reinterpret_cast<const ulonglong2*>(sC + k * 128);
        #pragma unroll
        for (int j = 0; j < 32; j++) {
            ulonglong2 bb = row[j];                  // broadcast, conflict-free
            q[2 * j]     = fma2(aa, bb.x, q[2 * j]);
            q[2 * j + 1] = fma2(aa, bb.y, q[2 * j + 1]);
        }
    }
    {
        const ull g2p = pk2(g2, g2);
        #pragma unroll
        for (int j = 0; j < 64; j++) q[j] = mul2(q[j], g2p);
        float x, y; upk2(q[t >> 1], x, y);
        if (t & 1) y += aab; else x += aab;
        q[t >> 1] = pk2(x, y);
    }

    // ---- step = 1 / (2 * ||Q||_F) ----
    {
        ull sacc = 0ULL;
        #pragma unroll
        for (int j = 0; j < 64; j++) sacc = fma2(q[j], q[j], sacc);
        float sx, sy; upk2(sacc, sx, sy);
        float ssq = wshfl_add(sx + sy);
        if (lane == 0) sR[wid] = ssq;
    }
    __syncthreads();
    const float Ssum = sR[0] + sR[1] + sR[2] + sR[3];
    const float step = 1.0f / (2.0f * sqrtf(Ssum));

    // ---- FISTA init ----
    sY[t] = 1.0f / 128.0f;
    sW[t] = 1.0f / 128.0f;
    if (t == 0) { sR[4] = 3.0e38f; sR[5] = 0.0f; }
    float tk = 1.0f;
    __syncthreads();

    for (int it = 0; it < N_ITERS; it++) {
        // ---- matvec: qy = Q[t][:] . y ----
        ull a0 = 0ULL, a1 = 0ULL, a2 = 0ULL, a3 = 0ULL;
        const ulonglong2* yy = reinterpret_cast<const ulonglong2*>(sY);
        #pragma unroll
        for (int j = 0; j < 16; j++) {
            ulonglong2 y0 = yy[2 * j];
            ulonglong2 y1 = yy[2 * j + 1];
            a0 = fma2(q[4 * j],     y0.x, a0);
            a1 = fma2(q[4 * j + 1], y0.y, a1);
            a2 = fma2(q[4 * j + 2], y1.x, a2);
            a3 = fma2(q[4 * j + 3], y1.y, a3);
        }
        a0 = add2(add2(a0, a1), add2(a2, a3));
        float ox, oy; upk2(a0, ox, oy);
        const float qy = ox + oy;

        const float yv = sY[t];
        const float v  = fmaf(-step, fmaf(2.0f, qy, -myret), yv);
        sV[t] = v;

        const float tn   = 0.5f * (1.0f + sqrtf(fmaf(4.0f * tk, tk, 1.0f)));
        const float coef = (tk - 1.0f) / tn;
        tk = tn;

        __syncthreads();   // v complete

        if (wid == (it & 3)) {
            // ---- capped-simplex projection of sV, warp-local ----
            const float4 v4 = reinterpret_cast<const float4*>(sV)[lane];
            const float4 w4 = reinterpret_cast<const float4*>(sW)[lane];
            const float4 y4 = reinterpret_cast<const float4*>(sY)[lane];

            // interleaved min/max butterfly (two independent shfl streams)
            float mn = fminf(fminf(v4.x, v4.y), fminf(v4.z, v4.w));
            float mx = fmaxf(fmaxf(v4.x, v4.y), fmaxf(v4.z, v4.w));
            #pragma unroll
            for (int o = 16; o > 0; o >>= 1) {
                float mns = __shfl_xor_sync(0xffffffffu, mn, o);
                float mxs = __shfl_xor_sync(0xffffffffu, mx, o);
                mn = fminf(mn, mns);
                mx = fmaxf(mx, mxs);
            }
            float lo = mn - MW;
            float hi = mx;

            float tau = sR[4];                       // warm start
            if (!(tau > lo && tau < hi)) tau = 0.5f * (lo + hi);

            // guarded Newton / active-set iteration on s(tau)=1
            #pragma unroll 1
            for (int n = 0; n < 24; n++) {
                float sv  = 0.0f;
                unsigned cnt = 0u;
                {
                    float z;
                    z = v4.x - tau; if (z > 0.0f && z < MW) { sv += v4.x; cnt += 1u; } else if (z >= MW) cnt += 4096u;
                    z = v4.y - tau; if (z > 0.0f && z < MW) { sv += v4.y; cnt += 1u; } else if (z >= MW) cnt += 4096u;
                    z = v4.z - tau; if (z > 0.0f && z < MW) { sv += v4.z; cnt += 1u; } else if (z >= MW) cnt += 4096u;
                    z = v4.w - tau; if (z > 0.0f && z < MW) { sv += v4.w; cnt += 1u; } else if (z >= MW) cnt += 4096u;
                }
                cnt = wredux_addu(cnt);              // 1 op (overlaps shfl chain)
                sv  = wshfl_add(sv);
                const int   nf = (int)(cnt & 4095u);
                const int   nu = (int)(cnt >> 12);
                const float s  = sv - (float)nf * tau + MW * (float)nu;
                if (s > 1.0f) lo = tau; else hi = tau;

                float tnew;
                if (nf > 0) tnew = (sv + MW * (float)nu - 1.0f) / (float)nf;
                else        tnew = 0.5f * (lo + hi);
                if (!(tnew > lo && tnew < hi)) tnew = 0.5f * (lo + hi);
                if (tnew == tau) break;              // active-set fixed point
                tau = tnew;
            }

            // final classification at tau + reference tau re-derivation
            float sv  = 0.0f;
            unsigned cnt = 0u;
            bool fr0, fr1, fr2, fr3, up0, up1, up2, up3;
            {
                float z;
                z = v4.x - tau; fr0 = (z > 0.0f) && (z < MW); up0 = (z >= MW);
                if (fr0) { sv += v4.x; cnt += 1u; } if (up0) cnt += 4096u;
                z = v4.y - tau; fr1 = (z > 0.0f) && (z < MW); up1 = (z >= MW);
                if (fr1) { sv += v4.y; cnt += 1u; } if (up1) cnt += 4096u;
                z = v4.z - tau; fr2 = (z > 0.0f) && (z < MW); up2 = (z >= MW);
                if (fr2) { sv += v4.z; cnt += 1u; } if (up2) cnt += 4096u;
                z = v4.w - tau; fr3 = (z > 0.0f) && (z < MW); up3 = (z >= MW);
                if (fr3) { sv += v4.w; cnt += 1u; } if (up3) cnt += 4096u;
            }
            cnt = wredux_addu(cnt);
            sv  = wshfl_add(sv);
            const int   nf    = (int)(cnt & 4095u);
            const int   nu    = (int)(cnt >> 12);
            const float nfree = (float)(nf > 0 ? nf : 1);
            const float tauf  = (sv + MW * (float)nu - 1.0f) / nfree;

            float4 wn, yn;
            wn.x = fr0 ? (v4.x - tauf) : (up0 ? MW : 0.0f);
            wn.y = fr1 ? (v4.y - tauf) : (up1 ? MW : 0.0f);
            wn.z = fr2 ? (v4.z - tauf) : (up2 ? MW : 0.0f);
            wn.w = fr3 ? (v4.w - tauf) : (up3 ? MW : 0.0f);
            yn.x = fmaf(coef, wn.x - w4.x, wn.x);
            yn.y = fmaf(coef, wn.y - w4.y, wn.y);
            yn.z = fmaf(coef, wn.z - w4.z, wn.z);
            yn.w = fmaf(coef, wn.w - w4.w, wn.w);

            reinterpret_cast<float4*>(sW)[lane] = wn;
            reinterpret_cast<float4*>(sY)[lane] = yn;
            if (lane == 0) sR[4] = tau;              // warm start

            // ---- bitwise-freeze detection: state will never change again ----
            bool same = (wn.x == w4.x) && (wn.y == w4.y) && (wn.z == w4.z) && (wn.w == w4.w)
                     && (w4.x == y4.x) && (w4.y == y4.y) && (w4.z == y4.z) && (w4.w == y4.w);
            unsigned bal = __ballot_sync(0xffffffffu, same);
            if (bal == 0xffffffffu && lane == 0) sR[5] = 1.0f;
        }
        __syncthreads();   // w, y ready for next iteration
        if (sR[5] != 0.0f) break;
    }

    out[b * N_DIM + t] = sW[t];
}

extern "C" void kernel_launch(void* const* d_in, const int* in_sizes, int n_in,
                              void* d_out, int out_size)
{
    const float* rets   = (const float*)d_in[0];
    const float* covmat = (const float*)d_in[1];
    const float* gsqrt  = (const float*)d_in[2];
    const float* alph   = (const float*)d_in[3];
    float*       out    = (float*)d_out;

    const int B = in_sizes[2];   // gamma_sqrt element count = batch
    const size_t smem_bytes = SMEM_FLOATS * sizeof(float);

    static bool attr_set = false;
    if (!attr_set) {
        cudaFuncSetAttribute(markowitz_kernel,
                             cudaFuncAttributeMaxDynamicSharedMemorySize,
                             (int)smem_bytes);
        attr_set = true;
    }

    markowitz_kernel<<<B, N_DIM, smem_bytes>>>(rets, covmat, gsqrt, alph, out);
}

// round 6
// speedup vs baseline: 2.3867x; 2.1959x over previous
#include <cuda_runtime.h>
#include <cstdint>

// NumericalMarkowitz: B=1024 items, N=128.
// 1 CTA (128 threads) per item. Thread t owns row t of Q as 64 packed f32x2
// registers. Matvec = 64 fma.rn.f32x2 per thread, no cross-thread reduce.
// Projection: warm-started two-point (Newton + midpoint) bracket search on the
// capped-simplex dual tau, one rotating warp. Fixed-point test happens BEFORE
// the bracket guard (R4's guard-order bug forced 24 passes every iteration).

typedef unsigned long long ull;

#define N_DIM   128
#define N_ITERS 300
#define MW      1.0f

__device__ __forceinline__ ull pk2(float x, float y) {
    ull r; asm("mov.b64 %0, {%1, %2};" : "=l"(r) : "f"(x), "f"(y)); return r;
}
__device__ __forceinline__ void upk2(ull a, float& x, float& y) {
    asm("mov.b64 {%0, %1}, %2;" : "=f"(x), "=f"(y) : "l"(a));
}
__device__ __forceinline__ ull fma2(ull a, ull b, ull c) {
    ull d; asm("fma.rn.f32x2 %0, %1, %2, %3;" : "=l"(d) : "l"(a), "l"(b), "l"(c)); return d;
}
__device__ __forceinline__ ull mul2(ull a, ull b) {
    ull d; asm("mul.rn.f32x2 %0, %1, %2;" : "=l"(d) : "l"(a), "l"(b)); return d;
}
__device__ __forceinline__ ull add2(ull a, ull b) {
    ull d; asm("add.rn.f32x2 %0, %1, %2;" : "=l"(d) : "l"(a), "l"(b)); return d;
}

__device__ __forceinline__ unsigned wredux_addu(unsigned v) {
    unsigned r; asm volatile("redux.sync.add.u32 %0, %1, 0xffffffff;" : "=r"(r) : "r"(v)); return r;
}
__device__ __forceinline__ float wshfl_add(float v) {
    #pragma unroll
    for (int o = 16; o > 0; o >>= 1) v += __shfl_xor_sync(0xffffffffu, v, o);
    return v;
}

// Dynamic smem layout (floats):
//   [0,16384)     : C tile
//   [16384,16512) : y
//   [16512,16640) : v
//   [16640,16768) : w
//   [16768,16776) : sR: [0..3] warp partials, [4] warm tau, [5] converged flag
#define SMEM_FLOATS (16384 + 128 + 128 + 128 + 8)

extern __shared__ float smem_f[];

__global__ void __launch_bounds__(128, 3)
markowitz_kernel(const float* __restrict__ rets,
                 const float* __restrict__ covmat,
                 const float* __restrict__ gamma_sqrt,
                 const float* __restrict__ alpha,
                 float* __restrict__ out)
{
    const int b    = blockIdx.x;
    const int t    = threadIdx.x;
    const int lane = t & 31;
    const int wid  = t >> 5;

    float* sC = smem_f;
    float* sY = smem_f + 16384;
    float* sV = sY + 128;
    float* sW = sV + 128;
    float* sR = sW + 128;

    // ---- load C tile (64KB) coalesced into smem ----
    {
        const float4* Cg  = reinterpret_cast<const float4*>(covmat + (size_t)b * (N_DIM * N_DIM));
        float4*       sC4 = reinterpret_cast<float4*>(sC);
        #pragma unroll
        for (int i = 0; i < 32; i++) sC4[i * 128 + t] = Cg[i * 128 + t];
    }
    const float myret = rets[b * N_DIM + t];
    const float g     = gamma_sqrt[b];
    const float g2    = g * g;
    const float aab   = fabsf(alpha[b]);
    __syncthreads();

    // ---- build Q row t ----
    ull q[64];
    #pragma unroll
    for (int j = 0; j < 64; j++) q[j] = 0ULL;

    for (int k = 0; k < N_DIM; k++) {
        const float a  = sC[k * 128 + t];
        const ull   aa = pk2(a, a);
        const ulonglong2* row = reinterpret_cast<const ulonglong2*>(sC + k * 128);
        #pragma unroll
        for (int j = 0; j < 32; j++) {
            ulonglong2 bb = row[j];
            q[2 * j]     = fma2(aa, bb.x, q[2 * j]);
            q[2 * j + 1] = fma2(aa, bb.y, q[2 * j + 1]);
        }
    }
    {
        const ull g2p = pk2(g2, g2);
        #pragma unroll
        for (int j = 0; j < 64; j++) q[j] = mul2(q[j], g2p);
        float x, y; upk2(q[t >> 1], x, y);
        if (t & 1) y += aab; else x += aab;
        q[t >> 1] = pk2(x, y);
    }

    // ---- step = 1 / (2 * ||Q||_F) ----
    {
        ull sacc = 0ULL;
        #pragma unroll
        for (int j = 0; j < 64; j++) sacc = fma2(q[j], q[j], sacc);
        float sx, sy; upk2(sacc, sx, sy);
        float ssq = wshfl_add(sx + sy);
        if (lane == 0) sR[wid] = ssq;
    }
    __syncthreads();
    const float Ssum = sR[0] + sR[1] + sR[2] + sR[3];
    const float step = 1.0f / (2.0f * sqrtf(Ssum));

    // ---- FISTA init ----
    sY[t] = 1.0f / 128.0f;
    sW[t] = 1.0f / 128.0f;
    if (t == 0) { sR[4] = 3.0e38f; sR[5] = 0.0f; }
    float tk = 1.0f;
    __syncthreads();

    for (int it = 0; it < N_ITERS; it++) {
        // ---- matvec: qy = Q[t][:] . y  (8 independent accumulator chains) ----
        ull a0 = 0ULL, a1 = 0ULL, a2 = 0ULL, a3 = 0ULL;
        ull a4 = 0ULL, a5 = 0ULL, a6 = 0ULL, a7 = 0ULL;
        const ulonglong2* yy = reinterpret_cast<const ulonglong2*>(sY);
        #pragma unroll
        for (int j = 0; j < 8; j++) {
            ulonglong2 y0 = yy[4 * j];
            ulonglong2 y1 = yy[4 * j + 1];
            ulonglong2 y2 = yy[4 * j + 2];
            ulonglong2 y3 = yy[4 * j + 3];
            a0 = fma2(q[8 * j],     y0.x, a0);
            a1 = fma2(q[8 * j + 1], y0.y, a1);
            a2 = fma2(q[8 * j + 2], y1.x, a2);
            a3 = fma2(q[8 * j + 3], y1.y, a3);
            a4 = fma2(q[8 * j + 4], y2.x, a4);
            a5 = fma2(q[8 * j + 5], y2.y, a5);
            a6 = fma2(q[8 * j + 6], y3.x, a6);
            a7 = fma2(q[8 * j + 7], y3.y, a7);
        }
        a0 = add2(add2(add2(a0, a1), add2(a2, a3)), add2(add2(a4, a5), add2(a6, a7)));
        float ox, oy; upk2(a0, ox, oy);
        const float qy = ox + oy;

        const float yv = sY[t];
        const float v  = fmaf(-step, fmaf(2.0f, qy, -myret), yv);
        sV[t] = v;

        const float tn   = 0.5f * (1.0f + sqrtf(fmaf(4.0f * tk, tk, 1.0f)));
        const float coef = (tk - 1.0f) / tn;
        tk = tn;

        __syncthreads();   // v complete

        if (wid == (it & 3)) {
            // ---- capped-simplex projection of sV, warp-local ----
            const float4 v4 = reinterpret_cast<const float4*>(sV)[lane];
            const float4 w4 = reinterpret_cast<const float4*>(sW)[lane];
            const float4 y4 = reinterpret_cast<const float4*>(sY)[lane];

            float mn = fminf(fminf(v4.x, v4.y), fminf(v4.z, v4.w));
            float mx = fmaxf(fmaxf(v4.x, v4.y), fmaxf(v4.z, v4.w));
            #pragma unroll
            for (int o = 16; o > 0; o >>= 1) {
                float mns = __shfl_xor_sync(0xffffffffu, mn, o);
                float mxs = __shfl_xor_sync(0xffffffffu, mx, o);
                mn = fminf(mn, mns);
                mx = fmaxf(mx, mxs);
            }
            float lo = mn - MW;
            float hi = mx;

            const float warm = sR[4];
            float tb  = 0.5f * (lo + hi);
            float ta  = (warm > lo && warm < hi) ? warm : tb;
            float tau = ta;
            bool  done = false;

            // two-point bracketed active-set search on s(tau) = 1
            #pragma unroll 1
            for (int n = 0; n < 16 && !done; n++) {
                float sva = 0.0f, svb = 0.0f;
                unsigned cnt = 0u;
                {
                    float z;
                    z = v4.x - ta; if (z > 0.0f && z < MW) { sva += v4.x; cnt += 1u; }         else if (z >= MW) cnt += (1u << 8);
                    z = v4.y - ta; if (z > 0.0f && z < MW) { sva += v4.y; cnt += 1u; }         else if (z >= MW) cnt += (1u << 8);
                    z = v4.z - ta; if (z > 0.0f && z < MW) { sva += v4.z; cnt += 1u; }         else if (z >= MW) cnt += (1u << 8);
                    z = v4.w - ta; if (z > 0.0f && z < MW) { sva += v4.w; cnt += 1u; }         else if (z >= MW) cnt += (1u << 8);
                    z = v4.x - tb; if (z > 0.0f && z < MW) { svb += v4.x; cnt += (1u << 16); } else if (z >= MW) cnt += (1u << 24);
                    z = v4.y - tb; if (z > 0.0f && z < MW) { svb += v4.y; cnt += (1u << 16); } else if (z >= MW) cnt += (1u << 24);
                    z = v4.z - tb; if (z > 0.0f && z < MW) { svb += v4.z; cnt += (1u << 16); } else if (z >= MW) cnt += (1u << 24);
                    z = v4.w - tb; if (z > 0.0f && z < MW) { svb += v4.w; cnt += (1u << 16); } else if (z >= MW) cnt += (1u << 24);
                }
                cnt = wredux_addu(cnt);              // both points, one op
                #pragma unroll
                for (int o = 16; o > 0; o >>= 1) {   // interleaved butterflies
                    float s1 = __shfl_xor_sync(0xffffffffu, sva, o);
                    float s2 = __shfl_xor_sync(0xffffffffu, svb, o);
                    sva += s1; svb += s2;
                }
                const int nfa = (int)(cnt & 255u);
                const int nua = (int)((cnt >> 8)  & 255u);
                const int nfb = (int)((cnt >> 16) & 255u);
                const int nub = (int)((cnt >> 24) & 255u);

                // fixed-point candidates (test BEFORE touching the bracket)
                const float na = (nfa > 0) ? (sva + (float)nua - 1.0f) / (float)nfa : ta;
                const float nb = (nfb > 0) ? (svb + (float)nub - 1.0f) / (float)nfb : tb;
                if (nfa > 0 && na == ta) { tau = ta; done = true; }
                else if (nfb > 0 && nb == tb) { tau = tb; done = true; }
                else {
                    // bracket update: s(t) monotone non-increasing in t
                    const float s_a = sva - (float)nfa * ta + (float)nua;
                    const float s_b = svb - (float)nfb * tb + (float)nub;
                    if (s_a > 1.0f) lo = fmaxf(lo, ta); else hi = fminf(hi, ta);
                    if (s_b > 1.0f) lo = fmaxf(lo, tb); else hi = fminf(hi, tb);
                    const float mid = 0.5f * (lo + hi);
                    float cand;
                    if      (nfa > 0 && na > lo && na < hi) cand = na;
                    else if (nfb > 0 && nb > lo && nb < hi) cand = nb;
                    else                                    cand = mid;
                    ta  = cand;
                    tb  = (cand == mid) ? 0.5f * (mid + hi) : mid;
                    tau = ta;
                }
            }

            // final classification at tau + reference tau re-derivation (exact)
            float sv  = 0.0f;
            unsigned cnt = 0u;
            bool fr0, fr1, fr2, fr3, up0, up1, up2, up3;
            {
                float z;
                z = v4.x - tau; fr0 = (z > 0.0f) && (z < MW); up0 = (z >= MW);
                if (fr0) { sv += v4.x; cnt += 1u; } if (up0) cnt += 4096u;
                z = v4.y - tau; fr1 = (z > 0.0f) && (z < MW); up1 = (z >= MW);
                if (fr1) { sv += v4.y; cnt += 1u; } if (up1) cnt += 4096u;
                z = v4.z - tau; fr2 = (z > 0.0f) && (z < MW); up2 = (z >= MW);
                if (fr2) { sv += v4.z; cnt += 1u; } if (up2) cnt += 4096u;
                z = v4.w - tau; fr3 = (z > 0.0f) && (z < MW); up3 = (z >= MW);
                if (fr3) { sv += v4.w; cnt += 1u; } if (up3) cnt += 4096u;
            }
            cnt = wredux_addu(cnt);
            sv  = wshfl_add(sv);
            const int   nf    = (int)(cnt & 4095u);
            const int   nu    = (int)(cnt >> 12);
            const float nfree = (float)(nf > 0 ? nf : 1);
            const float tauf  = (sv + MW * (float)nu - 1.0f) / nfree;

            float4 wn, yn;
            wn.x = fr0 ? (v4.x - tauf) : (up0 ? MW : 0.0f);
            wn.y = fr1 ? (v4.y - tauf) : (up1 ? MW : 0.0f);
            wn.z = fr2 ? (v4.z - tauf) : (up2 ? MW : 0.0f);
            wn.w = fr3 ? (v4.w - tauf) : (up3 ? MW : 0.0f);
            yn.x = fmaf(coef, wn.x - w4.x, wn.x);
            yn.y = fmaf(coef, wn.y - w4.y, wn.y);
            yn.z = fmaf(coef, wn.z - w4.z, wn.z);
            yn.w = fmaf(coef, wn.w - w4.w, wn.w);

            reinterpret_cast<float4*>(sW)[lane] = wn;
            reinterpret_cast<float4*>(sY)[lane] = yn;
            if (lane == 0) sR[4] = tau;              // warm start

            // bitwise-freeze early exit (exactly reproduces remaining iters)
            bool same = (wn.x == w4.x) && (wn.y == w4.y) && (wn.z == w4.z) && (wn.w == w4.w)
                     && (w4.x == y4.x) && (w4.y == y4.y) && (w4.z == y4.z) && (w4.w == y4.w);
            unsigned bal = __ballot_sync(0xffffffffu, same);
            if (bal == 0xffffffffu && lane == 0) sR[5] = 1.0f;
        }
        __syncthreads();   // w, y ready for next iteration
        if (sR[5] != 0.0f) break;
    }

    out[b * N_DIM + t] = sW[t];
}

extern "C" void kernel_launch(void* const* d_in, const int* in_sizes, int n_in,
                              void* d_out, int out_size)
{
    const float* rets   = (const float*)d_in[0];
    const float* covmat = (const float*)d_in[1];
    const float* gsqrt  = (const float*)d_in[2];
    const float* alph   = (const float*)d_in[3];
    float*       out    = (float*)d_out;

    const int B = in_sizes[2];
    const size_t smem_bytes = SMEM_FLOATS * sizeof(float);

    static bool attr_set = false;
    if (!attr_set) {
        cudaFuncSetAttribute(markowitz_kernel,
                             cudaFuncAttributeMaxDynamicSharedMemorySize,
                             (int)smem_bytes);
        attr_set = true;
    }

    markowitz_kernel<<<B, N_DIM, smem_bytes>>>(rets, covmat, gsqrt, alph, out);
}

// round 7
// speedup vs baseline: 2.8528x; 1.1953x over previous
#include <cuda_runtime.h>
#include <cstdint>

// NumericalMarkowitz: B=1024 items, N=128.
// 1 CTA (128 threads) per item. Thread t owns row t of Q as 64 packed f32x2
// registers. Matvec = 64 fma.rn.f32x2 per thread, 8 chains.
// Projection: warm-started bracketed active-set search; pass 0 fuses the
// min/max bracket with the first evaluation in one interleaved butterfly;
// fixed-point exits skip the final classification reduction entirely.

typedef unsigned long long ull;

#define N_DIM   128
#define N_ITERS 300
#define MW      1.0f

__device__ __forceinline__ ull pk2(float x, float y) {
    ull r; asm("mov.b64 %0, {%1, %2};" : "=l"(r) : "f"(x), "f"(y)); return r;
}
__device__ __forceinline__ void upk2(ull a, float& x, float& y) {
    asm("mov.b64 {%0, %1}, %2;" : "=f"(x), "=f"(y) : "l"(a));
}
__device__ __forceinline__ ull fma2(ull a, ull b, ull c) {
    ull d; asm("fma.rn.f32x2 %0, %1, %2, %3;" : "=l"(d) : "l"(a), "l"(b), "l"(c)); return d;
}
__device__ __forceinline__ ull mul2(ull a, ull b) {
    ull d; asm("mul.rn.f32x2 %0, %1, %2;" : "=l"(d) : "l"(a), "l"(b)); return d;
}
__device__ __forceinline__ ull add2(ull a, ull b) {
    ull d; asm("add.rn.f32x2 %0, %1, %2;" : "=l"(d) : "l"(a), "l"(b)); return d;
}

__device__ __forceinline__ unsigned wredux_addu(unsigned v) {
    unsigned r; asm volatile("redux.sync.add.u32 %0, %1, 0xffffffff;" : "=r"(r) : "r"(v)); return r;
}
__device__ __forceinline__ float wshfl_add(float v) {
    #pragma unroll
    for (int o = 16; o > 0; o >>= 1) v += __shfl_xor_sync(0xffffffffu, v, o);
    return v;
}

// Dynamic smem layout (floats):
//   [0,16384)     : C tile
//   [16384,16512) : y
//   [16512,16640) : v
//   [16640,16768) : w
//   [16768,16776) : sR: [0..3] warp partials, [4] warm tau, [5] converged flag
#define SMEM_FLOATS (16384 + 128 + 128 + 128 + 8)

extern __shared__ float smem_f[];

__global__ void __launch_bounds__(128, 3)
markowitz_kernel(const float* __restrict__ rets,
                 const float* __restrict__ covmat,
                 const float* __restrict__ gamma_sqrt,
                 const float* __restrict__ alpha,
                 float* __restrict__ out)
{
    const int b    = blockIdx.x;
    const int t    = threadIdx.x;
    const int lane = t & 31;
    const int wid  = t >> 5;

    float* sC = smem_f;
    float* sY = smem_f + 16384;
    float* sV = sY + 128;
    float* sW = sV + 128;
    float* sR = sW + 128;

    // ---- load C tile (64KB) coalesced into smem ----
    {
        const float4* Cg  = reinterpret_cast<const float4*>(covmat + (size_t)b * (N_DIM * N_DIM));
        float4*       sC4 = reinterpret_cast<float4*>(sC);
        #pragma unroll
        for (int i = 0; i < 32; i++) sC4[i * 128 + t] = Cg[i * 128 + t];
    }
    const float myret = rets[b * N_DIM + t];
    const float g     = gamma_sqrt[b];
    const float g2    = g * g;
    const float aab   = fabsf(alpha[b]);
    __syncthreads();

    // ---- build Q row t ----
    ull q[64];
    #pragma unroll
    for (int j = 0; j < 64; j++) q[j] = 0ULL;

    for (int k = 0; k < N_DIM; k++) {
        const float a  = sC[k * 128 + t];
        const ull   aa = pk2(a, a);
        const ulonglong2* row = reinterpret_cast<const ulonglong2*>(sC + k * 128);
        #pragma unroll
        for (int j = 0; j < 32; j++) {
            ulonglong2 bb = row[j];
            q[2 * j]     = fma2(aa, bb.x, q[2 * j]);
            q[2 * j + 1] = fma2(aa, bb.y, q[2 * j + 1]);
        }
    }
    {
        const ull g2p = pk2(g2, g2);
        #pragma unroll
        for (int j = 0; j < 64; j++) q[j] = mul2(q[j], g2p);
        float x, y; upk2(q[t >> 1], x, y);
        if (t & 1) y += aab; else x += aab;
        q[t >> 1] = pk2(x, y);
    }

    // ---- step = 1 / (2 * ||Q||_F) ----
    {
        ull sacc = 0ULL;
        #pragma unroll
        for (int j = 0; j < 64; j++) sacc = fma2(q[j], q[j], sacc);
        float sx, sy; upk2(sacc, sx, sy);
        float ssq = wshfl_add(sx + sy);
        if (lane == 0) sR[wid] = ssq;
    }
    __syncthreads();
    const float Ssum = sR[0] + sR[1] + sR[2] + sR[3];
    const float step = 1.0f / (2.0f * sqrtf(Ssum));

    // ---- FISTA init ----
    sY[t] = 1.0f / 128.0f;
    sW[t] = 1.0f / 128.0f;
    if (t == 0) { sR[4] = 0.0f; sR[5] = 0.0f; }   // warm tau seed = 0
    float tk = 1.0f;
    __syncthreads();

    for (int it = 0; it < N_ITERS; it++) {
        // ---- matvec: qy = Q[t][:] . y  (8 chains) ----
        ull a0 = 0ULL, a1 = 0ULL, a2 = 0ULL, a3 = 0ULL;
        ull a4 = 0ULL, a5 = 0ULL, a6 = 0ULL, a7 = 0ULL;
        const ulonglong2* yy = reinterpret_cast<const ulonglong2*>(sY);
        #pragma unroll
        for (int j = 0; j < 8; j++) {
            ulonglong2 y0 = yy[4 * j];
            ulonglong2 y1 = yy[4 * j + 1];
            ulonglong2 y2 = yy[4 * j + 2];
            ulonglong2 y3 = yy[4 * j + 3];
            a0 = fma2(q[8 * j],     y0.x, a0);
            a1 = fma2(q[8 * j + 1], y0.y, a1);
            a2 = fma2(q[8 * j + 2], y1.x, a2);
            a3 = fma2(q[8 * j + 3], y1.y, a3);
            a4 = fma2(q[8 * j + 4], y2.x, a4);
            a5 = fma2(q[8 * j + 5], y2.y, a5);
            a6 = fma2(q[8 * j + 6], y3.x, a6);
            a7 = fma2(q[8 * j + 7], y3.y, a7);
        }
        a0 = add2(add2(add2(a0, a1), add2(a2, a3)), add2(add2(a4, a5), add2(a6, a7)));
        float ox, oy; upk2(a0, ox, oy);
        const float qy = ox + oy;

        const float yv = sY[t];
        const float v  = fmaf(-step, fmaf(2.0f, qy, -myret), yv);
        sV[t] = v;

        const float tn   = 0.5f * (1.0f + sqrtf(fmaf(4.0f * tk, tk, 1.0f)));
        const float coef = (tk - 1.0f) / tn;
        tk = tn;

        __syncthreads();   // v complete

        if (wid == (it & 3)) {
            // ---- capped-simplex projection of sV, warp-local ----
            const float4 v4 = reinterpret_cast<const float4*>(sV)[lane];
            const float4 w4 = reinterpret_cast<const float4*>(sW)[lane];
            const float4 y4 = reinterpret_cast<const float4*>(sY)[lane];

            float ta  = sR[4];               // warm start (always a valid eval point)
            float tau = ta;
            bool  done = false;

            // ---- pass 0: fused {min, max, sum_free} butterfly + count redux ----
            float mn = fminf(fminf(v4.x, v4.y), fminf(v4.z, v4.w));
            float mx = fmaxf(fmaxf(v4.x, v4.y), fmaxf(v4.z, v4.w));
            float sva = 0.0f;
            unsigned cnt = 0u;
            {
                float z;
                z = v4.x - ta; if (z > 0.0f && z < MW) { sva += v4.x; cnt += 1u; } else if (z >= MW) cnt += (1u << 8);
                z = v4.y - ta; if (z > 0.0f && z < MW) { sva += v4.y; cnt += 1u; } else if (z >= MW) cnt += (1u << 8);
                z = v4.z - ta; if (z > 0.0f && z < MW) { sva += v4.z; cnt += 1u; } else if (z >= MW) cnt += (1u << 8);
                z = v4.w - ta; if (z > 0.0f && z < MW) { sva += v4.w; cnt += 1u; } else if (z >= MW) cnt += (1u << 8);
            }
            cnt = wredux_addu(cnt);
            #pragma unroll
            for (int o = 16; o > 0; o >>= 1) {   // 3 interleaved streams
                float s0 = __shfl_xor_sync(0xffffffffu, mn,  o);
                float s1 = __shfl_xor_sync(0xffffffffu, mx,  o);
                float s2 = __shfl_xor_sync(0xffffffffu, sva, o);
                mn = fminf(mn, s0); mx = fmaxf(mx, s1); sva += s2;
            }
            float lo = mn - MW;
            float hi = mx;
            {
                const int nfa = (int)(cnt & 255u);
                const int nua = (int)((cnt >> 8) & 255u);
                const float na = (nfa > 0) ? (sva + (float)nua - 1.0f) / (float)nfa : ta;
                if (nfa > 0 && na == ta) { done = true; }   // tau = ta already
                else {
                    const float s_a = sva - (float)nfa * ta + (float)nua;
                    if (s_a > 1.0f) lo = fmaxf(lo, ta); else hi = fminf(hi, ta);
                    const float mid = 0.5f * (lo + hi);
                    const float cand = (nfa > 0 && na > lo && na < hi) ? na : mid;
                    ta = cand;
                }
            }

            // ---- two-point bracketed active-set search ----
            if (!done) {
                float tb = 0.5f * (lo + hi);
                if (tb == ta) tb = 0.5f * (ta + hi);
                #pragma unroll 1
                for (int n = 0; n < 16 && !done; n++) {
                    float sa = 0.0f, sb = 0.0f;
                    unsigned c2 = 0u;
                    {
                        float z;
                        z = v4.x - ta; if (z > 0.0f && z < MW) { sa += v4.x; c2 += 1u; }         else if (z >= MW) c2 += (1u << 8);
                        z = v4.y - ta; if (z > 0.0f && z < MW) { sa += v4.y; c2 += 1u; }         else if (z >= MW) c2 += (1u << 8);
                        z = v4.z - ta; if (z > 0.0f && z < MW) { sa += v4.z; c2 += 1u; }         else if (z >= MW) c2 += (1u << 8);
                        z = v4.w - ta; if (z > 0.0f && z < MW) { sa += v4.w; c2 += 1u; }         else if (z >= MW) c2 += (1u << 8);
                        z = v4.x - tb; if (z > 0.0f && z < MW) { sb += v4.x; c2 += (1u << 16); } else if (z >= MW) c2 += (1u << 24);
                        z = v4.y - tb; if (z > 0.0f && z < MW) { sb += v4.y; c2 += (1u << 16); } else if (z >= MW) c2 += (1u << 24);
                        z = v4.z - tb; if (z > 0.0f && z < MW) { sb += v4.z; c2 += (1u << 16); } else if (z >= MW) c2 += (1u << 24);
                        z = v4.w - tb; if (z > 0.0f && z < MW) { sb += v4.w; c2 += (1u << 16); } else if (z >= MW) c2 += (1u << 24);
                    }
                    c2 = wredux_addu(c2);
                    #pragma unroll
                    for (int o = 16; o > 0; o >>= 1) {
                        float s1 = __shfl_xor_sync(0xffffffffu, sa, o);
                        float s2 = __shfl_xor_sync(0xffffffffu, sb, o);
                        sa += s1; sb += s2;
                    }
                    const int nfa = (int)(c2 & 255u);
                    const int nua = (int)((c2 >> 8)  & 255u);
                    const int nfb = (int)((c2 >> 16) & 255u);
                    const int nub = (int)((c2 >> 24) & 255u);

                    const float na = (nfa > 0) ? (sa + (float)nua - 1.0f) / (float)nfa : ta;
                    const float nb = (nfb > 0) ? (sb + (float)nub - 1.0f) / (float)nfb : tb;
                    if (nfa > 0 && na == ta)      { tau = ta; done = true; }
                    else if (nfb > 0 && nb == tb) { tau = tb; done = true; }
                    else {
                        const float s_a = sa - (float)nfa * ta + (float)nua;
                        const float s_b = sb - (float)nfb * tb + (float)nub;
                        if (s_a > 1.0f) lo = fmaxf(lo, ta); else hi = fminf(hi, ta);
                        if (s_b > 1.0f) lo = fmaxf(lo, tb); else hi = fminf(hi, tb);
                        const float mid = 0.5f * (lo + hi);
                        float cand;
                        if      (nfa > 0 && na > lo && na < hi) cand = na;
                        else if (nfb > 0 && nb > lo && nb < hi) cand = nb;
                        else                                    cand = mid;
                        ta  = cand;
                        tb  = (cand == mid) ? 0.5f * (mid + hi) : mid;
                        tau = ta;
                    }
                }
            }

            // ---- epilogue ----
            bool fr0, fr1, fr2, fr3, up0, up1, up2, up3;
            float tauf;
            {
                float z;
                z = v4.x - tau; fr0 = (z > 0.0f) && (z < MW); up0 = (z >= MW);
                z = v4.y - tau; fr1 = (z > 0.0f) && (z < MW); up1 = (z >= MW);
                z = v4.z - tau; fr2 = (z > 0.0f) && (z < MW); up2 = (z >= MW);
                z = v4.w - tau; fr3 = (z > 0.0f) && (z < MW); up3 = (z >= MW);
            }
            if (done) {
                // at the fixed point the re-derived tau IS tau (same formula, same set)
                tauf = tau;
            } else {
                float sv  = 0.0f;
                unsigned cf = 0u;
                if (fr0) { sv += v4.x; cf += 1u; } if (up0) cf += 4096u;
                if (fr1) { sv += v4.y; cf += 1u; } if (up1) cf += 4096u;
                if (fr2) { sv += v4.z; cf += 1u; } if (up2) cf += 4096u;
                if (fr3) { sv += v4.w; cf += 1u; } if (up3) cf += 4096u;
                cf = wredux_addu(cf);
                sv = wshfl_add(sv);
                const int   nf    = (int)(cf & 4095u);
                const int   nu    = (int)(cf >> 12);
                const float nfree = (float)(nf > 0 ? nf : 1);
                tauf = (sv + (float)nu - 1.0f) / nfree;
            }

            float4 wn, yn;
            wn.x = fr0 ? (v4.x - tauf) : (up0 ? MW : 0.0f);
            wn.y = fr1 ? (v4.y - tauf) : (up1 ? MW : 0.0f);
            wn.z = fr2 ? (v4.z - tauf) : (up2 ? MW : 0.0f);
            wn.w = fr3 ? (v4.w - tauf) : (up3 ? MW : 0.0f);
            yn.x = fmaf(coef, wn.x - w4.x, wn.x);
            yn.y = fmaf(coef, wn.y - w4.y, wn.y);
            yn.z = fmaf(coef, wn.z - w4.z, wn.z);
            yn.w = fmaf(coef, wn.w - w4.w, wn.w);

            reinterpret_cast<float4*>(sW)[lane] = wn;
            reinterpret_cast<float4*>(sY)[lane] = yn;
            if (lane == 0) sR[4] = tau;              // warm start

            // bitwise-freeze early exit (exactly reproduces remaining iters)
            bool same = (wn.x == w4.x) && (wn.y == w4.y) && (wn.z == w4.z) && (wn.w == w4.w)
                     && (w4.x == y4.x) && (w4.y == y4.y) && (w4.z == y4.z) && (w4.w == y4.w);
            unsigned bal = __ballot_sync(0xffffffffu, same);
            if (bal == 0xffffffffu && lane == 0) sR[5] = 1.0f;
        }
        __syncthreads();   // w, y ready for next iteration
        if (sR[5] != 0.0f) break;
    }

    out[b * N_DIM + t] = sW[t];
}

extern "C" void kernel_launch(void* const* d_in, const int* in_sizes, int n_in,
                              void* d_out, int out_size)
{
    const float* rets   = (const float*)d_in[0];
    const float* covmat = (const float*)d_in[1];
    const float* gsqrt  = (const float*)d_in[2];
    const float* alph   = (const float*)d_in[3];
    float*       out    = (float*)d_out;

    const int B = in_sizes[2];
    const size_t smem_bytes = SMEM_FLOATS * sizeof(float);

    static bool attr_set = false;
    if (!attr_set) {
        cudaFuncSetAttribute(markowitz_kernel,
                             cudaFuncAttributeMaxDynamicSharedMemorySize,
                             (int)smem_bytes);
        attr_set = true;
    }

    markowitz_kernel<<<B, N_DIM, smem_bytes>>>(rets, covmat, gsqrt, alph, out);
}

// round 12
// speedup vs baseline: 2.9691x; 1.0408x over previous
#include <cuda_runtime.h>
#include <cstdint>

// NumericalMarkowitz: B=1024 items, N=128.
// 1 CTA (128 threads) per item. Thread t owns row t of Q (64 f32x2 regs).
// Single CTA barrier per FISTA iteration: all 4 warps run the capped-simplex
// projection redundantly (identical arithmetic -> identical results), keep
// full w/y in registers, write y to smem redundantly, warm tau in a register.
// sV is double-buffered so warps can't race across iterations.

typedef unsigned long long ull;

#define N_DIM    128
#define N_ITERS  300
#define MW       1.0f
#define EXIT_TOL 2e-8f

__device__ __forceinline__ ull pk2(float x, float y) {
    ull r; asm("mov.b64 %0, {%1, %2};" : "=l"(r) : "f"(x), "f"(y)); return r;
}
__device__ __forceinline__ void upk2(ull a, float& x, float& y) {
    asm("mov.b64 {%0, %1}, %2;" : "=f"(x), "=f"(y) : "l"(a));
}
__device__ __forceinline__ ull fma2(ull a, ull b, ull c) {
    ull d; asm("fma.rn.f32x2 %0, %1, %2, %3;" : "=l"(d) : "l"(a), "l"(b), "l"(c)); return d;
}
__device__ __forceinline__ ull mul2(ull a, ull b) {
    ull d; asm("mul.rn.f32x2 %0, %1, %2;" : "=l"(d) : "l"(a), "l"(b)); return d;
}
__device__ __forceinline__ ull add2(ull a, ull b) {
    ull d; asm("add.rn.f32x2 %0, %1, %2;" : "=l"(d) : "l"(a), "l"(b)); return d;
}

__device__ __forceinline__ unsigned wredux_addu(unsigned v) {
    unsigned r; asm volatile("redux.sync.add.u32 %0, %1, 0xffffffff;" : "=r"(r) : "r"(v)); return r;
}
__device__ __forceinline__ float wshfl_add(float v) {
    #pragma unroll
    for (int o = 16; o > 0; o >>= 1) v += __shfl_xor_sync(0xffffffffu, v, o);
    return v;
}

// Dynamic smem layout (floats):
//   [0,16384)      : C tile
//   [16384,16512)  : y            (written redundantly by all warps)
//   [16512,16768)  : v[2]         (double buffer, 128 each)
//   [16768,16772)  : sR: warp partials for ||Q||_F
#define SMEM_FLOATS (16384 + 128 + 256 + 4)

extern __shared__ float smem_f[];

__global__ void __launch_bounds__(128, 3)
markowitz_kernel(const float* __restrict__ rets,
                 const float* __restrict__ covmat,
                 const float* __restrict__ gamma_sqrt,
                 const float* __restrict__ alpha,
                 float* __restrict__ out)
{
    const int b    = blockIdx.x;
    const int t    = threadIdx.x;
    const int lane = t & 31;
    const int wid  = t >> 5;

    float* sC = smem_f;
    float* sY = smem_f + 16384;
    float* sV = sY + 128;            // sV + 128*p is buffer p
    float* sR = sV + 256;

    // ---- load C tile (64KB) coalesced into smem ----
    {
        const float4* Cg  = reinterpret_cast<const float4*>(covmat + (size_t)b * (N_DIM * N_DIM));
        float4*       sC4 = reinterpret_cast<float4*>(sC);
        #pragma unroll
        for (int i = 0; i < 32; i++) sC4[i * 128 + t] = Cg[i * 128 + t];
    }
    const float myret = rets[b * N_DIM + t];
    const float g     = gamma_sqrt[b];
    const float g2    = g * g;
    const float aab   = fabsf(alpha[b]);
    __syncthreads();

    // ---- build Q row t ----
    ull q[64];
    #pragma unroll
    for (int j = 0; j < 64; j++) q[j] = 0ULL;

    for (int k = 0; k < N_DIM; k++) {
        const float a  = sC[k * 128 + t];
        const ull   aa = pk2(a, a);
        const ulonglong2* row = reinterpret_cast<const ulonglong2*>(sC + k * 128);
        #pragma unroll
        for (int j = 0; j < 32; j++) {
            ulonglong2 bb = row[j];
            q[2 * j]     = fma2(aa, bb.x, q[2 * j]);
            q[2 * j + 1] = fma2(aa, bb.y, q[2 * j + 1]);
        }
    }
    {
        const ull g2p = pk2(g2, g2);
        #pragma unroll
        for (int j = 0; j < 64; j++) q[j] = mul2(q[j], g2p);
        float x, y; upk2(q[t >> 1], x, y);
        if (t & 1) y += aab; else x += aab;
        q[t >> 1] = pk2(x, y);
    }

    // ---- step = 1 / (2 * ||Q||_F) ----
    {
        ull sacc = 0ULL;
        #pragma unroll
        for (int j = 0; j < 64; j++) sacc = fma2(q[j], q[j], sacc);
        float sx, sy; upk2(sacc, sx, sy);
        float ssq = wshfl_add(sx + sy);
        if (lane == 0) sR[wid] = ssq;
    }
    __syncthreads();
    const float Ssum = sR[0] + sR[1] + sR[2] + sR[3];
    const float step = 1.0f / (2.0f * sqrtf(Ssum));

    // ---- FISTA init: full w/y in registers per warp (4 coords per lane) ----
    float4 w4 = make_float4(1.0f/128.0f, 1.0f/128.0f, 1.0f/128.0f, 1.0f/128.0f);
    sY[t] = 1.0f / 128.0f;
    float warm = 0.0f;               // warm-start tau, register-resident
    float tk   = 1.0f;
    int   p    = 0;                  // sV buffer parity
    __syncthreads();

    #pragma unroll 1
    for (int it = 0; it < N_ITERS; it++) {
        // ---- step 1: matvec qy = Q[t][:] . y (8 chains), v_t -> sV[p] ----
        ull a0 = 0ULL, a1 = 0ULL, a2 = 0ULL, a3 = 0ULL;
        ull a4 = 0ULL, a5 = 0ULL, a6 = 0ULL, a7 = 0ULL;
        const ulonglong2* yy = reinterpret_cast<const ulonglong2*>(sY);
        #pragma unroll
        for (int j = 0; j < 8; j++) {
            ulonglong2 y0 = yy[4 * j];
            ulonglong2 y1 = yy[4 * j + 1];
            ulonglong2 y2 = yy[4 * j + 2];
            ulonglong2 y3 = yy[4 * j + 3];
            a0 = fma2(q[8 * j],     y0.x, a0);
            a1 = fma2(q[8 * j + 1], y0.y, a1);
            a2 = fma2(q[8 * j + 2], y1.x, a2);
            a3 = fma2(q[8 * j + 3], y1.y, a3);
            a4 = fma2(q[8 * j + 4], y2.x, a4);
            a5 = fma2(q[8 * j + 5], y2.y, a5);
            a6 = fma2(q[8 * j + 6], y3.x, a6);
            a7 = fma2(q[8 * j + 7], y3.y, a7);
        }
        a0 = add2(add2(add2(a0, a1), add2(a2, a3)), add2(add2(a4, a5), add2(a6, a7)));
        float ox, oy; upk2(a0, ox, oy);
        const float qy = ox + oy;
        const float yv = sY[t];
        sV[128 * p + t] = fmaf(-step, fmaf(2.0f, qy, -myret), yv);

        const float tn   = 0.5f * (1.0f + sqrtf(fmaf(4.0f * tk, tk, 1.0f)));
        const float coef = (tk - 1.0f) / tn;
        tk = tn;

        __syncthreads();             // the ONLY CTA barrier per iteration

        // ---- projection (all warps, redundant & identical) ----
        const float4 v4 = reinterpret_cast<const float4*>(sV + 128 * p)[lane];

        float ta  = warm;
        float tau = ta;
        bool  done = false;

        // pass 0: fused {min, max, sum_free} butterfly + count redux
        float mn = fminf(fminf(v4.x, v4.y), fminf(v4.z, v4.w));
        float mx = fmaxf(fmaxf(v4.x, v4.y), fmaxf(v4.z, v4.w));
        float sva = 0.0f;
        unsigned cnt = 0u;
        {
            float z;
            z = v4.x - ta; if (z > 0.0f && z < MW) { sva += v4.x; cnt += 1u; } else if (z >= MW) cnt += (1u << 8);
            z = v4.y - ta; if (z > 0.0f && z < MW) { sva += v4.y; cnt += 1u; } else if (z >= MW) cnt += (1u << 8);
            z = v4.z - ta; if (z > 0.0f && z < MW) { sva += v4.z; cnt += 1u; } else if (z >= MW) cnt += (1u << 8);
            z = v4.w - ta; if (z > 0.0f && z < MW) { sva += v4.w; cnt += 1u; } else if (z >= MW) cnt += (1u << 8);
        }
        cnt = wredux_addu(cnt);
        #pragma unroll
        for (int o = 16; o > 0; o >>= 1) {
            float s0 = __shfl_xor_sync(0xffffffffu, mn,  o);
            float s1 = __shfl_xor_sync(0xffffffffu, mx,  o);
            float s2 = __shfl_xor_sync(0xffffffffu, sva, o);
            mn = fminf(mn, s0); mx = fmaxf(mx, s1); sva += s2;
        }
        float lo = mn - MW;
        float hi = mx;
        {
            const int nfa = (int)(cnt & 255u);
            const int nua = (int)((cnt >> 8) & 255u);
            const float na = (nfa > 0) ? (sva + (float)nua - 1.0f) / (float)nfa : ta;
            if (nfa > 0 && na == ta) { done = true; }
            else {
                const float s_a = sva - (float)nfa * ta + (float)nua;
                if (s_a > 1.0f) lo = fmaxf(lo, ta); else hi = fminf(hi, ta);
                const float mid = 0.5f * (lo + hi);
                ta = (nfa > 0 && na > lo && na < hi) ? na : mid;
            }
        }

        // two-point bracketed active-set search
        if (!done) {
            float tb = 0.5f * (lo + hi);
            if (tb == ta) tb = 0.5f * (ta + hi);
            #pragma unroll 1
            for (int n = 0; n < 16 && !done; n++) {
                float sa = 0.0f, sb = 0.0f;
                unsigned c2 = 0u;
                {
                    float z;
                    z = v4.x - ta; if (z > 0.0f && z < MW) { sa += v4.x; c2 += 1u; }         else if (z >= MW) c2 += (1u << 8);
                    z = v4.y - ta; if (z > 0.0f && z < MW) { sa += v4.y; c2 += 1u; }         else if (z >= MW) c2 += (1u << 8);
                    z = v4.z - ta; if (z > 0.0f && z < MW) { sa += v4.z; c2 += 1u; }         else if (z >= MW) c2 += (1u << 8);
                    z = v4.w - ta; if (z > 0.0f && z < MW) { sa += v4.w; c2 += 1u; }         else if (z >= MW) c2 += (1u << 8);
                    z = v4.x - tb; if (z > 0.0f && z < MW) { sb += v4.x; c2 += (1u << 16); } else if (z >= MW) c2 += (1u << 24);
                    z = v4.y - tb; if (z > 0.0f && z < MW) { sb += v4.y; c2 += (1u << 16); } else if (z >= MW) c2 += (1u << 24);
                    z = v4.z - tb; if (z > 0.0f && z < MW) { sb += v4.z; c2 += (1u << 16); } else if (z >= MW) c2 += (1u << 24);
                    z = v4.w - tb; if (z > 0.0f && z < MW) { sb += v4.w; c2 += (1u << 16); } else if (z >= MW) c2 += (1u << 24);
                }
                c2 = wredux_addu(c2);
                #pragma unroll
                for (int o = 16; o > 0; o >>= 1) {
                    float s1 = __shfl_xor_sync(0xffffffffu, sa, o);
                    float s2 = __shfl_xor_sync(0xffffffffu, sb, o);
                    sa += s1; sb += s2;
                }
                const int nfa = (int)(c2 & 255u);
                const int nua = (int)((c2 >> 8)  & 255u);
                const int nfb = (int)((c2 >> 16) & 255u);
                const int nub = (int)((c2 >> 24) & 255u);

                const float na = (nfa > 0) ? (sa + (float)nua - 1.0f) / (float)nfa : ta;
                const float nb = (nfb > 0) ? (sb + (float)nub - 1.0f) / (float)nfb : tb;
                if (nfa > 0 && na == ta)      { tau = ta; done = true; }
                else if (nfb > 0 && nb == tb) { tau = tb; done = true; }
                else {
                    const float s_a = sa - (float)nfa * ta + (float)nua;
                    const float s_b = sb - (float)nfb * tb + (float)nub;
                    if (s_a > 1.0f) lo = fmaxf(lo, ta); else hi = fminf(hi, ta);
                    if (s_b > 1.0f) lo = fmaxf(lo, tb); else hi = fminf(hi, tb);
                    const float mid = 0.5f * (lo + hi);
                    float cand;
                    if      (nfa > 0 && na > lo && na < hi) cand = na;
                    else if (nfb > 0 && nb > lo && nb < hi) cand = nb;
                    else                                    cand = mid;
                    ta  = cand;
                    tb  = (cand == mid) ? 0.5f * (mid + hi) : mid;
                    tau = ta;
                }
            }
        }

        // ---- epilogue ----
        bool fr0, fr1, fr2, fr3, up0, up1, up2, up3;
        float tauf;
        {
            float z;
            z = v4.x - tau; fr0 = (z > 0.0f) && (z < MW); up0 = (z >= MW);
            z = v4.y - tau; fr1 = (z > 0.0f) && (z < MW); up1 = (z >= MW);
            z = v4.z - tau; fr2 = (z > 0.0f) && (z < MW); up2 = (z >= MW);
            z = v4.w - tau; fr3 = (z > 0.0f) && (z < MW); up3 = (z >= MW);
        }
        if (done) {
            tauf = tau;     // fixed point: re-derived tau IS tau
        } else {
            float sv  = 0.0f;
            unsigned cf = 0u;
            if (fr0) { sv += v4.x; cf += 1u; } if (up0) cf += 4096u;
            if (fr1) { sv += v4.y; cf += 1u; } if (up1) cf += 4096u;
            if (fr2) { sv += v4.z; cf += 1u; } if (up2) cf += 4096u;
            if (fr3) { sv += v4.w; cf += 1u; } if (up3) cf += 4096u;
            cf = wredux_addu(cf);
            sv = wshfl_add(sv);
            const int   nf    = (int)(cf & 4095u);
            const int   nu    = (int)(cf >> 12);
            const float nfree = (float)(nf > 0 ? nf : 1);
            tauf = (sv + (float)nu - 1.0f) / nfree;
        }

        float4 wn, yn;
        wn.x = fr0 ? (v4.x - tauf) : (up0 ? MW : 0.0f);
        wn.y = fr1 ? (v4.y - tauf) : (up1 ? MW : 0.0f);
        wn.z = fr2 ? (v4.z - tauf) : (up2 ? MW : 0.0f);
        wn.w = fr3 ? (v4.w - tauf) : (up3 ? MW : 0.0f);
        yn.x = fmaf(coef, wn.x - w4.x, wn.x);
        yn.y = fmaf(coef, wn.y - w4.y, wn.y);
        yn.z = fmaf(coef, wn.z - w4.z, wn.z);
        yn.w = fmaf(coef, wn.w - w4.w, wn.w);

        // redundant identical write of full y (benign same-value races)
        reinterpret_cast<float4*>(sY)[lane] = yn;
        warm = tau;

        // convergence: |dw| and |y-w| below EXIT_TOL on all coords, warp-uniform
        bool okc = (fabsf(wn.x - w4.x) <= EXIT_TOL) && (fabsf(wn.y - w4.y) <= EXIT_TOL)
                && (fabsf(wn.z - w4.z) <= EXIT_TOL) && (fabsf(wn.w - w4.w) <= EXIT_TOL)
                && (fabsf(yn.x - wn.x) <= EXIT_TOL) && (fabsf(yn.y - wn.y) <= EXIT_TOL)
                && (fabsf(yn.z - wn.z) <= EXIT_TOL) && (fabsf(yn.w - wn.w) <= EXIT_TOL);
        unsigned bal = __ballot_sync(0xffffffffu, okc);

        w4 = wn;
        p ^= 1;
        __syncwarp();                 // own y writes visible before next matvec

        if (bal == 0xffffffffu) break;   // identical decision in every warp
    }

    // every warp holds the full converged w; warp 0 writes the output
    if (wid == 0)
        reinterpret_cast<float4*>(out + (size_t)b * N_DIM)[lane] = w4;
}

extern "C" void kernel_launch(void* const* d_in, const int* in_sizes, int n_in,
                              void* d_out, int out_size)
{
    const float* rets   = (const float*)d_in[0];
    const float* covmat = (const float*)d_in[1];
    const float* gsqrt  = (const float*)d_in[2];
    const float* alph   = (const float*)d_in[3];
    float*       out    = (float*)d_out;

    const int B = in_sizes[2];
    const size_t smem_bytes = SMEM_FLOATS * sizeof(float);

    static bool attr_set = false;
    if (!attr_set) {
        cudaFuncSetAttribute(markowitz_kernel,
                             cudaFuncAttributeMaxDynamicSharedMemorySize,
                             (int)smem_bytes);
        attr_set = true;
    }

    markowitz_kernel<<<B, N_DIM, smem_bytes>>>(rets, covmat, gsqrt, alph, out);
}

// round 13
// speedup vs baseline: 3.8106x; 1.2834x over previous
#include <cuda_runtime.h>
#include <cstdint>

// NumericalMarkowitz: B=1024, N=128. 1 CTA (128 thr) per item; thread t owns
// row t of Q (64 f32x2 regs). One CTA barrier per FISTA iteration; all warps
// run the projection redundantly. Pass 0 computes the Newton candidate from
// the warm-started active set and VERIFIES it locally (mask stability + vote)
// -> one reduction butterfly per iteration in the common case.

typedef unsigned long long ull;

#define N_DIM    128
#define N_ITERS  300
#define MW       1.0f
#define EXIT_TOL 1e-7f

__device__ __forceinline__ ull pk2(float x, float y) {
    ull r; asm("mov.b64 %0, {%1, %2};" : "=l"(r) : "f"(x), "f"(y)); return r;
}
__device__ __forceinline__ void upk2(ull a, float& x, float& y) {
    asm("mov.b64 {%0, %1}, %2;" : "=f"(x), "=f"(y) : "l"(a));
}
__device__ __forceinline__ ull fma2(ull a, ull b, ull c) {
    ull d; asm("fma.rn.f32x2 %0, %1, %2, %3;" : "=l"(d) : "l"(a), "l"(b), "l"(c)); return d;
}
__device__ __forceinline__ ull mul2(ull a, ull b) {
    ull d; asm("mul.rn.f32x2 %0, %1, %2;" : "=l"(d) : "l"(a), "l"(b)); return d;
}
__device__ __forceinline__ ull add2(ull a, ull b) {
    ull d; asm("add.rn.f32x2 %0, %1, %2;" : "=l"(d) : "l"(a), "l"(b)); return d;
}
__device__ __forceinline__ unsigned wredux_addu(unsigned v) {
    unsigned r; asm volatile("redux.sync.add.u32 %0, %1, 0xffffffff;" : "=r"(r) : "r"(v)); return r;
}
__device__ __forceinline__ float wshfl_add(float v) {
    #pragma unroll
    for (int o = 16; o > 0; o >>= 1) v += __shfl_xor_sync(0xffffffffu, v, o);
    return v;
}

// Dynamic smem (floats): [0,16384) C; [16384,16512) y; [16512,16768) v[2];
// [16768,16772) warp partials for ||Q||_F
#define SMEM_FLOATS (16384 + 128 + 256 + 4)

extern __shared__ float smem_f[];

__global__ void __launch_bounds__(128, 3)
markowitz_kernel(const float* __restrict__ rets,
                 const float* __restrict__ covmat,
                 const float* __restrict__ gamma_sqrt,
                 const float* __restrict__ alpha,
                 float* __restrict__ out)
{
    const int b    = blockIdx.x;
    const int t    = threadIdx.x;
    const int lane = t & 31;
    const int wid  = t >> 5;

    float* sC = smem_f;
    float* sY = smem_f + 16384;
    float* sV = sY + 128;
    float* sR = sV + 256;

    // ---- load C tile ----
    {
        const float4* Cg  = reinterpret_cast<const float4*>(covmat + (size_t)b * (N_DIM * N_DIM));
        float4*       sC4 = reinterpret_cast<float4*>(sC);
        #pragma unroll
        for (int i = 0; i < 32; i++) sC4[i * 128 + t] = Cg[i * 128 + t];
    }
    const float myret = rets[b * N_DIM + t];
    const float g     = gamma_sqrt[b];
    const float g2    = g * g;
    const float aab   = fabsf(alpha[b]);
    __syncthreads();

    // ---- build Q row t ----
    ull q[64];
    #pragma unroll
    for (int j = 0; j < 64; j++) q[j] = 0ULL;

    for (int k = 0; k < N_DIM; k++) {
        const float a  = sC[k * 128 + t];
        const ull   aa = pk2(a, a);
        const ulonglong2* row = reinterpret_cast<const ulonglong2*>(sC + k * 128);
        #pragma unroll
        for (int j = 0; j < 32; j++) {
            ulonglong2 bb = row[j];
            q[2 * j]     = fma2(aa, bb.x, q[2 * j]);
            q[2 * j + 1] = fma2(aa, bb.y, q[2 * j + 1]);
        }
    }
    {
        const ull g2p = pk2(g2, g2);
        #pragma unroll
        for (int j = 0; j < 64; j++) q[j] = mul2(q[j], g2p);
        float x, y; upk2(q[t >> 1], x, y);
        if (t & 1) y += aab; else x += aab;
        q[t >> 1] = pk2(x, y);
    }

    // ---- step = 1 / (2 * ||Q||_F) ----
    {
        ull sacc = 0ULL;
        #pragma unroll
        for (int j = 0; j < 64; j++) sacc = fma2(q[j], q[j], sacc);
        float sx, sy; upk2(sacc, sx, sy);
        float ssq = wshfl_add(sx + sy);
        if (lane == 0) sR[wid] = ssq;
    }
    __syncthreads();
    const float Ssum = sR[0] + sR[1] + sR[2] + sR[3];
    const float step = 1.0f / (2.0f * sqrtf(Ssum));

    // ---- FISTA init ----
    float4 w4 = make_float4(1.0f/128.0f, 1.0f/128.0f, 1.0f/128.0f, 1.0f/128.0f);
    sY[t] = 1.0f / 128.0f;
    float warm = 0.0f;
    float tk   = 1.0f;
    int   p    = 0;
    __syncthreads();

    #pragma unroll 1
    for (int it = 0; it < N_ITERS; it++) {
        // ---- matvec ----
        ull a0 = 0ULL, a1 = 0ULL, a2 = 0ULL, a3 = 0ULL;
        ull a4 = 0ULL, a5 = 0ULL, a6 = 0ULL, a7 = 0ULL;
        const ulonglong2* yy = reinterpret_cast<const ulonglong2*>(sY);
        #pragma unroll
        for (int j = 0; j < 8; j++) {
            ulonglong2 y0 = yy[4 * j];
            ulonglong2 y1 = yy[4 * j + 1];
            ulonglong2 y2 = yy[4 * j + 2];
            ulonglong2 y3 = yy[4 * j + 3];
            a0 = fma2(q[8 * j],     y0.x, a0);
            a1 = fma2(q[8 * j + 1], y0.y, a1);
            a2 = fma2(q[8 * j + 2], y1.x, a2);
            a3 = fma2(q[8 * j + 3], y1.y, a3);
            a4 = fma2(q[8 * j + 4], y2.x, a4);
            a5 = fma2(q[8 * j + 5], y2.y, a5);
            a6 = fma2(q[8 * j + 6], y3.x, a6);
            a7 = fma2(q[8 * j + 7], y3.y, a7);
        }
        a0 = add2(add2(add2(a0, a1), add2(a2, a3)), add2(add2(a4, a5), add2(a6, a7)));
        float ox, oy; upk2(a0, ox, oy);
        const float qy = ox + oy;
        const float yv = sY[t];
        sV[128 * p + t] = fmaf(-step, fmaf(2.0f, qy, -myret), yv);

        const float tn   = 0.5f * (1.0f + sqrtf(fmaf(4.0f * tk, tk, 1.0f)));
        const float coef = (tk - 1.0f) / tn;
        tk = tn;

        __syncthreads();             // the ONLY CTA barrier per iteration

        // ---- projection (all warps, redundant & identical) ----
        const float4 v4 = reinterpret_cast<const float4*>(sV + 128 * p)[lane];

        // local eval: masks packed into one byte + contributions
        auto evalm = [&](float tt, unsigned& mloc, float& ls, unsigned& cc) {
            float z; bool f0,f1,f2,f3,u0,u1,u2,u3;
            z = v4.x - tt; f0 = (z > 0.0f) && (z < MW); u0 = (z >= MW);
            z = v4.y - tt; f1 = (z > 0.0f) && (z < MW); u1 = (z >= MW);
            z = v4.z - tt; f2 = (z > 0.0f) && (z < MW); u2 = (z >= MW);
            z = v4.w - tt; f3 = (z > 0.0f) && (z < MW); u3 = (z >= MW);
            ls = 0.0f; cc = 0u;
            if (f0) { ls += v4.x; cc += 1u; } if (u0) cc += (1u << 8);
            if (f1) { ls += v4.y; cc += 1u; } if (u1) cc += (1u << 8);
            if (f2) { ls += v4.z; cc += 1u; } if (u2) cc += (1u << 8);
            if (f3) { ls += v4.w; cc += 1u; } if (u3) cc += (1u << 8);
            mloc = (unsigned)f0 | ((unsigned)f1 << 1) | ((unsigned)f2 << 2) | ((unsigned)f3 << 3)
                 | ((unsigned)u0 << 4) | ((unsigned)u1 << 5) | ((unsigned)u2 << 6) | ((unsigned)u3 << 7);
        };
        // masks-only (no sums) for local verify
        auto maskonly = [&](float tt) -> unsigned {
            float z; unsigned m = 0u;
            z = v4.x - tt; m |= (unsigned)((z > 0.0f) && (z < MW)) | ((unsigned)(z >= MW) << 4);
            z = v4.y - tt; m |= ((unsigned)((z > 0.0f) && (z < MW)) << 1) | ((unsigned)(z >= MW) << 5);
            z = v4.z - tt; m |= ((unsigned)((z > 0.0f) && (z < MW)) << 2) | ((unsigned)(z >= MW) << 6);
            z = v4.w - tt; m |= ((unsigned)((z > 0.0f) && (z < MW)) << 3) | ((unsigned)(z >= MW) << 7);
            return m;
        };

        float tau = warm;
        bool  done = false;
        unsigned mfin = 0u;          // masks at final tau
        float tauf;

        // ---- pass 0: eval at warm tau, Newton candidate, LOCAL verify ----
        unsigned m_a, c_a; float ls_a;
        evalm(warm, m_a, ls_a, c_a);
        c_a = wredux_addu(c_a);
        float sv = wshfl_add(ls_a);
        const int nf0 = (int)(c_a & 255u);
        const int nu0 = (int)((c_a >> 8) & 255u);
        float na = warm;
        if (nf0 > 0) {
            na = (sv + (float)nu0 - 1.0f) / (float)nf0;
            const unsigned m_na = maskonly(na);
            if (__all_sync(0xffffffffu, m_na == m_a)) {
                done = true; tau = na; tauf = na; mfin = m_na;
            }
        }

        if (!done) {
            // ---- fallback: bracket + single-point verified search ----
            float mn = fminf(fminf(v4.x, v4.y), fminf(v4.z, v4.w));
            float mx = fmaxf(fmaxf(v4.x, v4.y), fmaxf(v4.z, v4.w));
            #pragma unroll
            for (int o = 16; o > 0; o >>= 1) {
                float s0 = __shfl_xor_sync(0xffffffffu, mn, o);
                float s1 = __shfl_xor_sync(0xffffffffu, mx, o);
                mn = fminf(mn, s0); mx = fmaxf(mx, s1);
            }
            float lo = mn - MW;
            float hi = mx;
            {
                const float s_a = sv - (float)nf0 * warm + (float)nu0;
                if (s_a > 1.0f) lo = fmaxf(lo, warm); else hi = fminf(hi, warm);
            }
            float tc = (nf0 > 0 && na > lo && na < hi) ? na : 0.5f * (lo + hi);

            unsigned m_c = 0u; unsigned c_c; float ls_c;
            #pragma unroll 1
            for (int n = 0; n < 24 && !done; n++) {
                evalm(tc, m_c, ls_c, c_c);
                c_c = wredux_addu(c_c);
                float s2 = wshfl_add(ls_c);
                const int nf2 = (int)(c_c & 255u);
                const int nu2 = (int)((c_c >> 8) & 255u);
                if (nf2 > 0) {
                    const float na2 = (s2 + (float)nu2 - 1.0f) / (float)nf2;
                    const unsigned m_na2 = maskonly(na2);
                    if (__all_sync(0xffffffffu, m_na2 == m_c)) {
                        done = true; tau = na2; tauf = na2; mfin = m_na2;
                    } else {
                        const float s_c = s2 - (float)nf2 * tc + (float)nu2;
                        if (s_c > 1.0f) lo = fmaxf(lo, tc); else hi = fminf(hi, tc);
                        tc = (na2 > lo && na2 < hi) ? na2 : 0.5f * (lo + hi);
                    }
                } else {
                    const float s_c = (float)nu2;   // no free coords
                    if (s_c > 1.0f) lo = fmaxf(lo, tc); else hi = fminf(hi, tc);
                    tc = 0.5f * (lo + hi);
                }
            }

            if (!done) {
                // exact reference epilogue at tau = tc
                evalm(tc, m_c, ls_c, c_c);
                c_c = wredux_addu(c_c);
                float s2 = wshfl_add(ls_c);
                const int   nf2   = (int)(c_c & 255u);
                const int   nu2   = (int)((c_c >> 8) & 255u);
                const float nfree = (float)(nf2 > 0 ? nf2 : 1);
                tau  = tc;
                tauf = (s2 + (float)nu2 - 1.0f) / nfree;
                mfin = m_c;
            }
        }

        // ---- build w, y from final masks ----
        const bool fr0 = mfin & 1u,  fr1 = mfin & 2u,  fr2 = mfin & 4u,  fr3 = mfin & 8u;
        const bool up0 = mfin & 16u, up1 = mfin & 32u, up2 = mfin & 64u, up3 = mfin & 128u;

        float4 wn, yn;
        wn.x = fr0 ? (v4.x - tauf) : (up0 ? MW : 0.0f);
        wn.y = fr1 ? (v4.y - tauf) : (up1 ? MW : 0.0f);
        wn.z = fr2 ? (v4.z - tauf) : (up2 ? MW : 0.0f);
        wn.w = fr3 ? (v4.w - tauf) : (up3 ? MW : 0.0f);
        yn.x = fmaf(coef, wn.x - w4.x, wn.x);
        yn.y = fmaf(coef, wn.y - w4.y, wn.y);
        yn.z = fmaf(coef, wn.z - w4.z, wn.z);
        yn.w = fmaf(coef, wn.w - w4.w, wn.w);

        reinterpret_cast<float4*>(sY)[lane] = yn;   // redundant identical write
        warm = tau;

        bool okc = (fabsf(wn.x - w4.x) <= EXIT_TOL) && (fabsf(wn.y - w4.y) <= EXIT_TOL)
                && (fabsf(wn.z - w4.z) <= EXIT_TOL) && (fabsf(wn.w - w4.w) <= EXIT_TOL)
                && (fabsf(yn.x - wn.x) <= EXIT_TOL) && (fabsf(yn.y - wn.y) <= EXIT_TOL)
                && (fabsf(yn.z - wn.z) <= EXIT_TOL) && (fabsf(yn.w - wn.w) <= EXIT_TOL);
        const int allok = __all_sync(0xffffffffu, okc);

        w4 = wn;
        p ^= 1;
        __syncwarp();

        if (allok) break;            // identical decision in every warp
    }

    if (wid == 0)
        reinterpret_cast<float4*>(out + (size_t)b * N_DIM)[lane] = w4;
}

extern "C" void kernel_launch(void* const* d_in, const int* in_sizes, int n_in,
                              void* d_out, int out_size)
{
    const float* rets   = (const float*)d_in[0];
    const float* covmat = (const float*)d_in[1];
    const float* gsqrt  = (const float*)d_in[2];
    const float* alph   = (const float*)d_in[3];
    float*       out    = (float*)d_out;

    const int B = in_sizes[2];
    const size_t smem_bytes = SMEM_FLOATS * sizeof(float);

    static bool attr_set = false;
    if (!attr_set) {
        cudaFuncSetAttribute(markowitz_kernel,
                             cudaFuncAttributeMaxDynamicSharedMemorySize,
                             (int)smem_bytes);
        attr_set = true;
    }

    markowitz_kernel<<<B, N_DIM, smem_bytes>>>(rets, covmat, gsqrt, alph, out);
}